// round 13
// baseline (speedup 1.0000x reference)
#include <cuda_runtime.h>
#include <cuda_fp16.h>

#define Nn 50000
#define Ee 800000
#define Hh 128
#define Gg 1024
#define EPSb 1e-5f

// ---------------- static device scratch (device-code use only) -------------
__device__ int    d_cnt[Nn];
__device__ int    d_cur[Nn];
__device__ int    d_rowptr[Nn + 1];
__device__ float  d_dinv[Nn];
__device__ int    d_colidx[Ee];
__device__ float  d_wedge[Ee];
__device__ uint4  d_hbufh[(size_t)Nn * 16];    // N x 128 features, fp16 packed
__device__ float4 d_aggbuf4[(size_t)Nn * 32];  // N x 128 features, fp32
__device__ float  d_colsum[3 * Hh];            // per-layer BN sums
__device__ float  d_colsq[3 * Hh];
__device__ float  d_pooled[Gg * 256];

// ---------------- init: zero counters + all stat buffers -------------------
__global__ void k_zero_all() {
    int i = blockIdx.x * blockDim.x + threadIdx.x;
    if (i < Nn) { d_cnt[i] = 0; d_cur[i] = 0; }
    if (i < 3 * Hh) { d_colsum[i] = 0.f; d_colsq[i] = 0.f; }
}

// ---------------- CSR construction (edge_index is int32) -------------------
__device__ __forceinline__ int clampN(int v) {
    return v < 0 ? 0 : (v >= Nn ? Nn - 1 : v);
}

__global__ void k_count(const int* __restrict__ ei) {
    int e = blockIdx.x * blockDim.x + threadIdx.x;
    if (e < Ee) atomicAdd(&d_cnt[clampN(ei[Ee + e])], 1);
}

__global__ void k_scan() {   // 1 block, 1024 threads
    __shared__ int ssum[1024];
    int t = threadIdx.x;
    const int CH = (Nn + 1023) / 1024;   // 49
    int b = t * CH;
    int e = min(b + CH, Nn);
    int s = 0;
    for (int i = b; i < e; i++) s += d_cnt[i];
    ssum[t] = s;
    __syncthreads();
    for (int off = 1; off < 1024; off <<= 1) {
        int v = (t >= off) ? ssum[t - off] : 0;
        __syncthreads();
        ssum[t] += v;
        __syncthreads();
    }
    int run = (t > 0) ? ssum[t - 1] : 0;
    for (int i = b; i < e; i++) {
        int c = d_cnt[i];
        d_rowptr[i] = run;
        run += c;
        d_dinv[i] = rsqrtf((float)(c + 1));
    }
    if (t == 0) d_rowptr[Nn] = Ee;
}

__global__ void k_fill(const int* __restrict__ ei) {
    int e = blockIdx.x * blockDim.x + threadIdx.x;
    if (e < Ee) {
        int src = clampN(ei[e]);
        int dst = clampN(ei[Ee + e]);
        int pos = d_rowptr[dst] + atomicAdd(&d_cur[dst], 1);
        d_colidx[pos] = src;
        d_wedge[pos] = d_dinv[src] * d_dinv[dst];
    }
}

// ---------------- GEMM core (R9 measured-good; fp16 packed output) ---------
// block: 256 threads, 64 rows x 128 cols. thread micro-tile: 4 rows x 8 cols.
__device__ __forceinline__ void gemm_core(float (&Xs)[64][129],
                                          float (&Ws)[16][128],
                                          const float* __restrict__ W,
                                          int row0, int tid) {
    int rc = tid & 15, cc = tid >> 4;
    int r0 = rc * 4, c0 = cc * 8;
    float acc[4][8];
#pragma unroll
    for (int i = 0; i < 4; i++)
#pragma unroll
        for (int j = 0; j < 8; j++) acc[i][j] = 0.f;

    for (int kc = 0; kc < 8; kc++) {
        __syncthreads();
        for (int i = tid; i < 16 * 32; i += 256) {
            int kk = i >> 5, c4 = i & 31;
            float4 w = ((const float4*)W)[(size_t)(kc * 16 + kk) * 32 + c4];
            Ws[kk][c4 * 4 + 0] = w.x; Ws[kk][c4 * 4 + 1] = w.y;
            Ws[kk][c4 * 4 + 2] = w.z; Ws[kk][c4 * 4 + 3] = w.w;
        }
        __syncthreads();
#pragma unroll
        for (int kk = 0; kk < 16; kk++) {
            int k = kc * 16 + kk;
            float x0 = Xs[r0 + 0][k];
            float x1 = Xs[r0 + 1][k];
            float x2 = Xs[r0 + 2][k];
            float x3 = Xs[r0 + 3][k];
#pragma unroll
            for (int j = 0; j < 8; j++) {
                float w = Ws[kk][c0 + j];
                acc[0][j] = fmaf(x0, w, acc[0][j]);
                acc[1][j] = fmaf(x1, w, acc[1][j]);
                acc[2][j] = fmaf(x2, w, acc[2][j]);
                acc[3][j] = fmaf(x3, w, acc[3][j]);
            }
        }
    }

#pragma unroll
    for (int i = 0; i < 4; i++) {
        int gr = row0 + r0 + i;
        if (gr < Nn) {
            __half2 p0 = __float22half2_rn(make_float2(acc[i][0], acc[i][1]));
            __half2 p1 = __float22half2_rn(make_float2(acc[i][2], acc[i][3]));
            __half2 p2 = __float22half2_rn(make_float2(acc[i][4], acc[i][5]));
            __half2 p3 = __float22half2_rn(make_float2(acc[i][6], acc[i][7]));
            uint4 pk;
            pk.x = *(unsigned int*)&p0;
            pk.y = *(unsigned int*)&p1;
            pk.z = *(unsigned int*)&p2;
            pk.w = *(unsigned int*)&p3;
            d_hbufh[(size_t)gr * 16 + cc] = pk;   // 8 fp16 cols at c0
        }
    }
}

// layer 0: X = external input
__global__ __launch_bounds__(256) void k_gemm0(const float* __restrict__ Xin,
                                               const float* __restrict__ W) {
    __shared__ float Xs[64][129];
    __shared__ float Ws[16][128];
    int tid = threadIdx.x;
    int row0 = blockIdx.x * 64;

    for (int i = tid; i < 64 * 32; i += 256) {
        int r = i >> 5, c4 = i & 31;
        int gr = row0 + r;
        float4 v = make_float4(0.f, 0.f, 0.f, 0.f);
        if (gr < Nn) v = ((const float4*)Xin)[(size_t)gr * 32 + c4];
        int c = c4 * 4;
        Xs[r][c + 0] = v.x; Xs[r][c + 1] = v.y;
        Xs[r][c + 2] = v.z; Xs[r][c + 3] = v.w;
    }
    gemm_core(Xs, Ws, W, row0, tid);
}

// layers 1,2: X = d_aggbuf4 (fp32) with fused BN(from stats slot sl)+ReLU
__global__ __launch_bounds__(256) void k_gemm_bn(const float* __restrict__ W,
                                                 const float* __restrict__ gamma,
                                                 const float* __restrict__ beta,
                                                 int sl) {
    __shared__ float Xs[64][129];
    __shared__ float Ws[16][128];
    __shared__ float ssc[128], ssh[128];
    int tid = threadIdx.x;
    int row0 = blockIdx.x * 64;

    if (tid < 128) {   // compute BN scale/shift from layer-sl statistics
        float mean = d_colsum[sl * Hh + tid] * (1.f / (float)Nn);
        float var = d_colsq[sl * Hh + tid] * (1.f / (float)Nn) - mean * mean;
        var = fmaxf(var, 0.f);
        float sc = gamma[tid] * rsqrtf(var + EPSb);
        ssc[tid] = sc;
        ssh[tid] = beta[tid] - mean * sc;
    }
    __syncthreads();

    for (int i = tid; i < 64 * 32; i += 256) {
        int r = i >> 5, c4 = i & 31;
        int gr = row0 + r;
        float4 v = make_float4(0.f, 0.f, 0.f, 0.f);
        if (gr < Nn) v = d_aggbuf4[(size_t)gr * 32 + c4];
        int c = c4 * 4;
        Xs[r][c + 0] = fmaxf(fmaf(v.x, ssc[c + 0], ssh[c + 0]), 0.f);
        Xs[r][c + 1] = fmaxf(fmaf(v.y, ssc[c + 1], ssh[c + 1]), 0.f);
        Xs[r][c + 2] = fmaxf(fmaf(v.z, ssc[c + 2], ssh[c + 2]), 0.f);
        Xs[r][c + 3] = fmaxf(fmaf(v.w, ssc[c + 3], ssh[c + 3]), 0.f);
    }
    gemm_core(Xs, Ws, W, row0, tid);
}

// --------- gather aggregation (fp16 reads) + fused BN statistics -----------
// one warp per node; lane handles 4 feature cols (one uint2 = 4 fp16).
__global__ __launch_bounds__(256) void k_aggstats(int layer) {
    __shared__ float4 psum[8][32];
    __shared__ float4 psq[8][32];
    int tid = threadIdx.x;
    int warp = tid >> 5, lane = tid & 31;
    int n = blockIdx.x * 8 + warp;
    const uint2* hb2 = (const uint2*)d_hbufh;

    float4 acc = make_float4(0.f, 0.f, 0.f, 0.f);
    if (n < Nn) {
        float di = d_dinv[n];
        float w0 = di * di;
        {
            uint2 hu = hb2[(size_t)n * 32 + lane];
            float2 f0 = __half22float2(*reinterpret_cast<__half2*>(&hu.x));
            float2 f1 = __half22float2(*reinterpret_cast<__half2*>(&hu.y));
            acc.x = f0.x * w0; acc.y = f0.y * w0;
            acc.z = f1.x * w0; acc.w = f1.y * w0;
        }

        int beg = d_rowptr[n], end = d_rowptr[n + 1];
        for (int base = beg; base < end; base += 32) {
            int m = min(32, end - base);
            int s = 0; float w = 0.f;
            if (lane < m) { s = d_colidx[base + lane]; w = d_wedge[base + lane]; }
            for (int j = 0; j < m; j++) {
                int sj = __shfl_sync(0xffffffffu, s, j);
                float wj = __shfl_sync(0xffffffffu, w, j);
                uint2 hu = hb2[(size_t)sj * 32 + lane];
                float2 f0 = __half22float2(*reinterpret_cast<__half2*>(&hu.x));
                float2 f1 = __half22float2(*reinterpret_cast<__half2*>(&hu.y));
                acc.x = fmaf(f0.x, wj, acc.x);
                acc.y = fmaf(f0.y, wj, acc.y);
                acc.z = fmaf(f1.x, wj, acc.z);
                acc.w = fmaf(f1.y, wj, acc.w);
            }
        }
        d_aggbuf4[(size_t)n * 32 + lane] = acc;
    }

    psum[warp][lane] = acc;
    psq[warp][lane] = make_float4(acc.x * acc.x, acc.y * acc.y,
                                  acc.z * acc.z, acc.w * acc.w);
    __syncthreads();

    if (tid < 128) {
        int c4 = tid >> 2, comp = tid & 3;
        float s = 0.f, q = 0.f;
#pragma unroll
        for (int w = 0; w < 8; w++) {
            const float* a = (const float*)&psum[w][c4];
            const float* b = (const float*)&psq[w][c4];
            s += a[comp];
            q += b[comp];
        }
        atomicAdd(&d_colsum[layer * Hh + tid], s);
        atomicAdd(&d_colsq[layer * Hh + tid], q);
    }
}

// ---------------- pooling: one block per graph, binary search --------------
// applies layer-2 BN+ReLU inline; batch is int32, sorted.
__global__ __launch_bounds__(128) void k_pool(const int* __restrict__ batch,
                                              const float* __restrict__ gamma,
                                              const float* __restrict__ beta) {
    __shared__ int sbound[2];
    int g = blockIdx.x;
    int t = threadIdx.x;   // t = feature col
    if (t < 2) {
        int target = g + t;  // lower_bound(target)
        int lo = 0, hi = Nn;
        while (lo < hi) {
            int mid = (lo + hi) >> 1;
            if (batch[mid] < target) lo = mid + 1;
            else hi = mid;
        }
        sbound[t] = lo;
    }
    float mean = d_colsum[2 * Hh + t] * (1.f / (float)Nn);
    float var = d_colsq[2 * Hh + t] * (1.f / (float)Nn) - mean * mean;
    var = fmaxf(var, 0.f);
    float sc = gamma[t] * rsqrtf(var + EPSb);
    float sh = beta[t] - mean * sc;
    __syncthreads();

    int lo = sbound[0], hi = sbound[1];
    const float* agg = (const float*)d_aggbuf4;
    float rsum = 0.f, rmax = 0.f;
    for (int n = lo; n < hi; n++) {
        float v = fmaxf(fmaf(agg[(size_t)n * 128 + t], sc, sh), 0.f);
        rsum += v;
        rmax = fmaxf(rmax, v);
    }
    int cnt = hi - lo;
    d_pooled[g * 256 + t] = (cnt > 0) ? rsum / (float)cnt : 0.f;
    d_pooled[g * 256 + 128 + t] = (cnt > 0) ? rmax : 0.f;
}

// ---------------- MLP head: 8 graphs per block -----------------------------
#define GPG 8
__global__ __launch_bounds__(256) void k_mlp(const float* __restrict__ mW1,
                                             const float* __restrict__ mb1,
                                             const float* __restrict__ mW2,
                                             const float* __restrict__ mb2,
                                             const float* __restrict__ mW3,
                                             const float* __restrict__ mb3,
                                             float* __restrict__ out) {
    __shared__ float sg[GPG][256];
    __shared__ float h1[GPG][256];
    __shared__ float h2[GPG][128];
    int t = threadIdx.x;
    int g0 = blockIdx.x * GPG;

#pragma unroll
    for (int g = 0; g < GPG; g++)
        sg[g][t] = d_pooled[(g0 + g) * 256 + t];
    __syncthreads();

    {
        float acc[GPG];
        float b = mb1[t];
#pragma unroll
        for (int g = 0; g < GPG; g++) acc[g] = b;
        for (int k = 0; k < 256; k++) {
            float wv = mW1[k * 256 + t];
#pragma unroll
            for (int g = 0; g < GPG; g++) acc[g] = fmaf(sg[g][k], wv, acc[g]);
        }
#pragma unroll
        for (int g = 0; g < GPG; g++) h1[g][t] = fmaxf(acc[g], 0.f);
    }
    __syncthreads();

    if (t < 128) {
        float acc[GPG];
        float b = mb2[t];
#pragma unroll
        for (int g = 0; g < GPG; g++) acc[g] = b;
        for (int k = 0; k < 256; k++) {
            float wv = mW2[k * 128 + t];
#pragma unroll
            for (int g = 0; g < GPG; g++) acc[g] = fmaf(h1[g][k], wv, acc[g]);
        }
#pragma unroll
        for (int g = 0; g < GPG; g++) h2[g][t] = fmaxf(acc[g], 0.f);
    }
    __syncthreads();

    if (t < GPG) {
        float a = mb3[0];
        for (int i = 0; i < 128; i++) a = fmaf(h2[t][i], mW3[i], a);
        out[g0 + t] = a;
    }
}

// ---------------- launcher: fork CSR build parallel to layer-0 GEMM --------
extern "C" void kernel_launch(void* const* d_in, const int* in_sizes, int n_in,
                              void* d_out, int out_size) {
    const float* x      = (const float*)d_in[0];
    const int* ei       = (const int*)d_in[1];     // int32
    const int* batch    = (const int*)d_in[2];     // int32, sorted
    const float* convW0 = (const float*)d_in[3];
    const float* convW  = (const float*)d_in[4];
    // d_in[5] = convb : cancels inside batchnorm, unused
    const float* gamma  = (const float*)d_in[6];
    const float* beta   = (const float*)d_in[7];
    const float* mW1    = (const float*)d_in[8];
    const float* mb1    = (const float*)d_in[9];
    const float* mW2    = (const float*)d_in[10];
    const float* mb2    = (const float*)d_in[11];
    const float* mW3    = (const float*)d_in[12];
    const float* mb3    = (const float*)d_in[13];
    float* out = (float*)d_out;

    // side stream + events created once (host handles; no device memory)
    static cudaStream_t s2 = nullptr;
    static cudaEvent_t evFork = nullptr, evJoin = nullptr;
    if (s2 == nullptr) {
        cudaStreamCreateWithFlags(&s2, cudaStreamNonBlocking);
        cudaEventCreateWithFlags(&evFork, cudaEventDisableTiming);
        cudaEventCreateWithFlags(&evJoin, cudaEventDisableTiming);
    }

    const int GEMM_GRID = (Nn + 63) / 64;   // 782
    const int AGG_GRID = (Nn + 7) / 8;      // 6250

    // fork: CSR build on s2, layer-0 GEMM on origin stream (independent)
    cudaEventRecord(evFork, 0);
    cudaStreamWaitEvent(s2, evFork, 0);

    k_zero_all<<<(Nn + 255) / 256, 256, 0, s2>>>();
    k_count<<<(Ee + 255) / 256, 256, 0, s2>>>(ei);
    k_scan<<<1, 1024, 0, s2>>>();
    k_fill<<<(Ee + 255) / 256, 256, 0, s2>>>(ei);
    cudaEventRecord(evJoin, s2);

    k_gemm0<<<GEMM_GRID, 256>>>(x, convW0);

    // join: aggregation needs both h (origin) and CSR (s2)
    cudaStreamWaitEvent(0, evJoin, 0);

    // layer 0
    k_aggstats<<<AGG_GRID, 256>>>(0);
    // layer 1
    k_gemm_bn<<<GEMM_GRID, 256>>>(convW + 0 * Hh * Hh, gamma + 0 * Hh, beta + 0 * Hh, 0);
    k_aggstats<<<AGG_GRID, 256>>>(1);
    // layer 2
    k_gemm_bn<<<GEMM_GRID, 256>>>(convW + 1 * Hh * Hh, gamma + 1 * Hh, beta + 1 * Hh, 1);
    k_aggstats<<<AGG_GRID, 256>>>(2);

    // pooling (applies layer-2 BN) + MLP
    k_pool<<<Gg, 128>>>(batch, gamma + 2 * Hh, beta + 2 * Hh);
    k_mlp<<<Gg / GPG, 256>>>(mW1, mb1, mW2, mb2, mW3, mb3, out);
}

// round 14
// speedup vs baseline: 1.0220x; 1.0220x over previous
#include <cuda_runtime.h>
#include <cuda_fp16.h>

#define Nn 50000
#define Ee 800000
#define Hh 128
#define Gg 1024
#define EPSb 1e-5f

// ---------------- static device scratch (device-code use only) -------------
__device__ int    d_cnt[Nn];
__device__ int    d_cur[Nn];
__device__ int    d_rowptr[Nn + 1];
__device__ float  d_dinv[Nn];
__device__ int    d_colidx[Ee];
__device__ uint4  d_hbufh[(size_t)Nn * 16];    // N x 128 features, fp16 packed
__device__ float4 d_aggbuf4[(size_t)Nn * 32];  // N x 128 features, fp32
__device__ float  d_colsum[3 * Hh];            // per-layer BN sums
__device__ float  d_colsq[3 * Hh];
__device__ float  d_pooled[Gg * 256];

// ---------------- init: zero counters + all stat buffers -------------------
__global__ void k_zero_all() {
    int i = blockIdx.x * blockDim.x + threadIdx.x;
    if (i < Nn) { d_cnt[i] = 0; d_cur[i] = 0; }
    if (i < 3 * Hh) { d_colsum[i] = 0.f; d_colsq[i] = 0.f; }
}

// ---------------- CSR construction (edge_index is int32) -------------------
__device__ __forceinline__ int clampN(int v) {
    return v < 0 ? 0 : (v >= Nn ? Nn - 1 : v);
}

__global__ void k_count(const int* __restrict__ ei) {
    int e = blockIdx.x * blockDim.x + threadIdx.x;
    if (e < Ee) atomicAdd(&d_cnt[clampN(ei[Ee + e])], 1);
}

__global__ void k_scan() {   // 1 block, 1024 threads
    __shared__ int ssum[1024];
    int t = threadIdx.x;
    const int CH = (Nn + 1023) / 1024;   // 49
    int b = t * CH;
    int e = min(b + CH, Nn);
    int s = 0;
    for (int i = b; i < e; i++) s += d_cnt[i];
    ssum[t] = s;
    __syncthreads();
    for (int off = 1; off < 1024; off <<= 1) {
        int v = (t >= off) ? ssum[t - off] : 0;
        __syncthreads();
        ssum[t] += v;
        __syncthreads();
    }
    int run = (t > 0) ? ssum[t - 1] : 0;
    for (int i = b; i < e; i++) {
        int c = d_cnt[i];
        d_rowptr[i] = run;
        run += c;
        d_dinv[i] = rsqrtf((float)(c + 1));
    }
    if (t == 0) d_rowptr[Nn] = Ee;
}

// fill: only colidx now (wedge factored out algebraically)
__global__ void k_fill(const int* __restrict__ ei) {
    int e = blockIdx.x * blockDim.x + threadIdx.x;
    if (e < Ee) {
        int src = clampN(ei[e]);
        int dst = clampN(ei[Ee + e]);
        int pos = d_rowptr[dst] + atomicAdd(&d_cur[dst], 1);
        d_colidx[pos] = src;
    }
}

// ---------------- GEMM core (R9 measured-good; fp16 packed output) ---------
// block: 256 threads, 64 rows x 128 cols. thread micro-tile: 4 rows x 8 cols.
__device__ __forceinline__ void gemm_core(float (&Xs)[64][129],
                                          float (&Ws)[16][128],
                                          const float* __restrict__ W,
                                          int row0, int tid) {
    int rc = tid & 15, cc = tid >> 4;
    int r0 = rc * 4, c0 = cc * 8;
    float acc[4][8];
#pragma unroll
    for (int i = 0; i < 4; i++)
#pragma unroll
        for (int j = 0; j < 8; j++) acc[i][j] = 0.f;

    for (int kc = 0; kc < 8; kc++) {
        __syncthreads();
        for (int i = tid; i < 16 * 32; i += 256) {
            int kk = i >> 5, c4 = i & 31;
            float4 w = ((const float4*)W)[(size_t)(kc * 16 + kk) * 32 + c4];
            Ws[kk][c4 * 4 + 0] = w.x; Ws[kk][c4 * 4 + 1] = w.y;
            Ws[kk][c4 * 4 + 2] = w.z; Ws[kk][c4 * 4 + 3] = w.w;
        }
        __syncthreads();
#pragma unroll
        for (int kk = 0; kk < 16; kk++) {
            int k = kc * 16 + kk;
            float x0 = Xs[r0 + 0][k];
            float x1 = Xs[r0 + 1][k];
            float x2 = Xs[r0 + 2][k];
            float x3 = Xs[r0 + 3][k];
#pragma unroll
            for (int j = 0; j < 8; j++) {
                float w = Ws[kk][c0 + j];
                acc[0][j] = fmaf(x0, w, acc[0][j]);
                acc[1][j] = fmaf(x1, w, acc[1][j]);
                acc[2][j] = fmaf(x2, w, acc[2][j]);
                acc[3][j] = fmaf(x3, w, acc[3][j]);
            }
        }
    }

#pragma unroll
    for (int i = 0; i < 4; i++) {
        int gr = row0 + r0 + i;
        if (gr < Nn) {
            __half2 p0 = __float22half2_rn(make_float2(acc[i][0], acc[i][1]));
            __half2 p1 = __float22half2_rn(make_float2(acc[i][2], acc[i][3]));
            __half2 p2 = __float22half2_rn(make_float2(acc[i][4], acc[i][5]));
            __half2 p3 = __float22half2_rn(make_float2(acc[i][6], acc[i][7]));
            uint4 pk;
            pk.x = *(unsigned int*)&p0;
            pk.y = *(unsigned int*)&p1;
            pk.z = *(unsigned int*)&p2;
            pk.w = *(unsigned int*)&p3;
            d_hbufh[(size_t)gr * 16 + cc] = pk;   // 8 fp16 cols at c0
        }
    }
}

// layer 0: X = external input
__global__ __launch_bounds__(256) void k_gemm0(const float* __restrict__ Xin,
                                               const float* __restrict__ W) {
    __shared__ float Xs[64][129];
    __shared__ float Ws[16][128];
    int tid = threadIdx.x;
    int row0 = blockIdx.x * 64;

    for (int i = tid; i < 64 * 32; i += 256) {
        int r = i >> 5, c4 = i & 31;
        int gr = row0 + r;
        float4 v = make_float4(0.f, 0.f, 0.f, 0.f);
        if (gr < Nn) v = ((const float4*)Xin)[(size_t)gr * 32 + c4];
        int c = c4 * 4;
        Xs[r][c + 0] = v.x; Xs[r][c + 1] = v.y;
        Xs[r][c + 2] = v.z; Xs[r][c + 3] = v.w;
    }
    gemm_core(Xs, Ws, W, row0, tid);
}

// layers 1,2: X = d_aggbuf4 (fp32) with fused BN(from stats slot sl)+ReLU
__global__ __launch_bounds__(256) void k_gemm_bn(const float* __restrict__ W,
                                                 const float* __restrict__ gamma,
                                                 const float* __restrict__ beta,
                                                 int sl) {
    __shared__ float Xs[64][129];
    __shared__ float Ws[16][128];
    __shared__ float ssc[128], ssh[128];
    int tid = threadIdx.x;
    int row0 = blockIdx.x * 64;

    if (tid < 128) {   // compute BN scale/shift from layer-sl statistics
        float mean = d_colsum[sl * Hh + tid] * (1.f / (float)Nn);
        float var = d_colsq[sl * Hh + tid] * (1.f / (float)Nn) - mean * mean;
        var = fmaxf(var, 0.f);
        float sc = gamma[tid] * rsqrtf(var + EPSb);
        ssc[tid] = sc;
        ssh[tid] = beta[tid] - mean * sc;
    }
    __syncthreads();

    for (int i = tid; i < 64 * 32; i += 256) {
        int r = i >> 5, c4 = i & 31;
        int gr = row0 + r;
        float4 v = make_float4(0.f, 0.f, 0.f, 0.f);
        if (gr < Nn) v = d_aggbuf4[(size_t)gr * 32 + c4];
        int c = c4 * 4;
        Xs[r][c + 0] = fmaxf(fmaf(v.x, ssc[c + 0], ssh[c + 0]), 0.f);
        Xs[r][c + 1] = fmaxf(fmaf(v.y, ssc[c + 1], ssh[c + 1]), 0.f);
        Xs[r][c + 2] = fmaxf(fmaf(v.z, ssc[c + 2], ssh[c + 2]), 0.f);
        Xs[r][c + 3] = fmaxf(fmaf(v.w, ssc[c + 3], ssh[c + 3]), 0.f);
    }
    gemm_core(Xs, Ws, W, row0, tid);
}

// --------- gather aggregation (fp16 reads) + fused BN statistics -----------
// one warp per node; lane handles 4 feature cols (one uint2 = 4 fp16).
// weight = dinv[src] (dinv[n] factored out of the sum); 2 neighbors/iter.
__global__ __launch_bounds__(256) void k_aggstats(int layer) {
    __shared__ float4 psum[8][32];
    __shared__ float4 psq[8][32];
    int tid = threadIdx.x;
    int warp = tid >> 5, lane = tid & 31;
    int n = blockIdx.x * 8 + warp;
    const uint2* hb2 = (const uint2*)d_hbufh;

    float4 acc = make_float4(0.f, 0.f, 0.f, 0.f);
    if (n < Nn) {
        float di = d_dinv[n];
        {   // self loop: weight inside the factored sum is dinv[n]
            uint2 hu = hb2[(size_t)n * 32 + lane];
            float2 f0 = __half22float2(*reinterpret_cast<__half2*>(&hu.x));
            float2 f1 = __half22float2(*reinterpret_cast<__half2*>(&hu.y));
            acc.x = f0.x * di; acc.y = f0.y * di;
            acc.z = f1.x * di; acc.w = f1.y * di;
        }
        float4 acc2 = make_float4(0.f, 0.f, 0.f, 0.f);

        int beg = d_rowptr[n], end = d_rowptr[n + 1];
        for (int base = beg; base < end; base += 32) {
            int m = min(32, end - base);
            int s = 0; float w = 0.f;
            if (lane < m) {
                s = d_colidx[base + lane];
                w = d_dinv[s];
            }
            int j = 0;
            for (; j + 1 < m; j += 2) {
                int sA = __shfl_sync(0xffffffffu, s, j);
                float wA = __shfl_sync(0xffffffffu, w, j);
                int sB = __shfl_sync(0xffffffffu, s, j + 1);
                float wB = __shfl_sync(0xffffffffu, w, j + 1);
                uint2 huA = hb2[(size_t)sA * 32 + lane];
                uint2 huB = hb2[(size_t)sB * 32 + lane];
                float2 a0 = __half22float2(*reinterpret_cast<__half2*>(&huA.x));
                float2 a1 = __half22float2(*reinterpret_cast<__half2*>(&huA.y));
                float2 b0 = __half22float2(*reinterpret_cast<__half2*>(&huB.x));
                float2 b1 = __half22float2(*reinterpret_cast<__half2*>(&huB.y));
                acc.x = fmaf(a0.x, wA, acc.x);
                acc.y = fmaf(a0.y, wA, acc.y);
                acc.z = fmaf(a1.x, wA, acc.z);
                acc.w = fmaf(a1.y, wA, acc.w);
                acc2.x = fmaf(b0.x, wB, acc2.x);
                acc2.y = fmaf(b0.y, wB, acc2.y);
                acc2.z = fmaf(b1.x, wB, acc2.z);
                acc2.w = fmaf(b1.y, wB, acc2.w);
            }
            if (j < m) {
                int sA = __shfl_sync(0xffffffffu, s, j);
                float wA = __shfl_sync(0xffffffffu, w, j);
                uint2 huA = hb2[(size_t)sA * 32 + lane];
                float2 a0 = __half22float2(*reinterpret_cast<__half2*>(&huA.x));
                float2 a1 = __half22float2(*reinterpret_cast<__half2*>(&huA.y));
                acc.x = fmaf(a0.x, wA, acc.x);
                acc.y = fmaf(a0.y, wA, acc.y);
                acc.z = fmaf(a1.x, wA, acc.z);
                acc.w = fmaf(a1.y, wA, acc.w);
            }
        }
        // merge + final scale by dinv[n]
        acc.x = (acc.x + acc2.x) * di;
        acc.y = (acc.y + acc2.y) * di;
        acc.z = (acc.z + acc2.z) * di;
        acc.w = (acc.w + acc2.w) * di;
        d_aggbuf4[(size_t)n * 32 + lane] = acc;
    }

    psum[warp][lane] = acc;
    psq[warp][lane] = make_float4(acc.x * acc.x, acc.y * acc.y,
                                  acc.z * acc.z, acc.w * acc.w);
    __syncthreads();

    if (tid < 128) {
        int c4 = tid >> 2, comp = tid & 3;
        float s = 0.f, q = 0.f;
#pragma unroll
        for (int w = 0; w < 8; w++) {
            const float* a = (const float*)&psum[w][c4];
            const float* b = (const float*)&psq[w][c4];
            s += a[comp];
            q += b[comp];
        }
        atomicAdd(&d_colsum[layer * Hh + tid], s);
        atomicAdd(&d_colsq[layer * Hh + tid], q);
    }
}

// ---------------- pooling: one block per graph, binary search --------------
// applies layer-2 BN+ReLU inline; batch is int32, sorted.
__global__ __launch_bounds__(128) void k_pool(const int* __restrict__ batch,
                                              const float* __restrict__ gamma,
                                              const float* __restrict__ beta) {
    __shared__ int sbound[2];
    int g = blockIdx.x;
    int t = threadIdx.x;   // t = feature col
    if (t < 2) {
        int target = g + t;  // lower_bound(target)
        int lo = 0, hi = Nn;
        while (lo < hi) {
            int mid = (lo + hi) >> 1;
            if (batch[mid] < target) lo = mid + 1;
            else hi = mid;
        }
        sbound[t] = lo;
    }
    float mean = d_colsum[2 * Hh + t] * (1.f / (float)Nn);
    float var = d_colsq[2 * Hh + t] * (1.f / (float)Nn) - mean * mean;
    var = fmaxf(var, 0.f);
    float sc = gamma[t] * rsqrtf(var + EPSb);
    float sh = beta[t] - mean * sc;
    __syncthreads();

    int lo = sbound[0], hi = sbound[1];
    const float* agg = (const float*)d_aggbuf4;
    float rsum = 0.f, rmax = 0.f;
    for (int n = lo; n < hi; n++) {
        float v = fmaxf(fmaf(agg[(size_t)n * 128 + t], sc, sh), 0.f);
        rsum += v;
        rmax = fmaxf(rmax, v);
    }
    int cnt = hi - lo;
    d_pooled[g * 256 + t] = (cnt > 0) ? rsum / (float)cnt : 0.f;
    d_pooled[g * 256 + 128 + t] = (cnt > 0) ? rmax : 0.f;
}

// ---------------- MLP head: 8 graphs per block -----------------------------
#define GPG 8
__global__ __launch_bounds__(256) void k_mlp(const float* __restrict__ mW1,
                                             const float* __restrict__ mb1,
                                             const float* __restrict__ mW2,
                                             const float* __restrict__ mb2,
                                             const float* __restrict__ mW3,
                                             const float* __restrict__ mb3,
                                             float* __restrict__ out) {
    __shared__ float sg[GPG][256];
    __shared__ float h1[GPG][256];
    __shared__ float h2[GPG][128];
    int t = threadIdx.x;
    int g0 = blockIdx.x * GPG;

#pragma unroll
    for (int g = 0; g < GPG; g++)
        sg[g][t] = d_pooled[(g0 + g) * 256 + t];
    __syncthreads();

    {
        float acc[GPG];
        float b = mb1[t];
#pragma unroll
        for (int g = 0; g < GPG; g++) acc[g] = b;
        for (int k = 0; k < 256; k++) {
            float wv = mW1[k * 256 + t];
#pragma unroll
            for (int g = 0; g < GPG; g++) acc[g] = fmaf(sg[g][k], wv, acc[g]);
        }
#pragma unroll
        for (int g = 0; g < GPG; g++) h1[g][t] = fmaxf(acc[g], 0.f);
    }
    __syncthreads();

    if (t < 128) {
        float acc[GPG];
        float b = mb2[t];
#pragma unroll
        for (int g = 0; g < GPG; g++) acc[g] = b;
        for (int k = 0; k < 256; k++) {
            float wv = mW2[k * 128 + t];
#pragma unroll
            for (int g = 0; g < GPG; g++) acc[g] = fmaf(h1[g][k], wv, acc[g]);
        }
#pragma unroll
        for (int g = 0; g < GPG; g++) h2[g][t] = fmaxf(acc[g], 0.f);
    }
    __syncthreads();

    if (t < GPG) {
        float a = mb3[0];
        for (int i = 0; i < 128; i++) a = fmaf(h2[t][i], mW3[i], a);
        out[g0 + t] = a;
    }
}

// ---------------- launcher (single stream; fork was measured neutral) ------
extern "C" void kernel_launch(void* const* d_in, const int* in_sizes, int n_in,
                              void* d_out, int out_size) {
    const float* x      = (const float*)d_in[0];
    const int* ei       = (const int*)d_in[1];     // int32
    const int* batch    = (const int*)d_in[2];     // int32, sorted
    const float* convW0 = (const float*)d_in[3];
    const float* convW  = (const float*)d_in[4];
    // d_in[5] = convb : cancels inside batchnorm, unused
    const float* gamma  = (const float*)d_in[6];
    const float* beta   = (const float*)d_in[7];
    const float* mW1    = (const float*)d_in[8];
    const float* mb1    = (const float*)d_in[9];
    const float* mW2    = (const float*)d_in[10];
    const float* mb2    = (const float*)d_in[11];
    const float* mW3    = (const float*)d_in[12];
    const float* mb3    = (const float*)d_in[13];
    float* out = (float*)d_out;

    // CSR construction
    k_zero_all<<<(Nn + 255) / 256, 256>>>();
    k_count<<<(Ee + 255) / 256, 256>>>(ei);
    k_scan<<<1, 1024>>>();
    k_fill<<<(Ee + 255) / 256, 256>>>(ei);

    const int GEMM_GRID = (Nn + 63) / 64;   // 782
    const int AGG_GRID = (Nn + 7) / 8;      // 6250

    // layer 0
    k_gemm0<<<GEMM_GRID, 256>>>(x, convW0);
    k_aggstats<<<AGG_GRID, 256>>>(0);
    // layer 1
    k_gemm_bn<<<GEMM_GRID, 256>>>(convW + 0 * Hh * Hh, gamma + 0 * Hh, beta + 0 * Hh, 0);
    k_aggstats<<<AGG_GRID, 256>>>(1);
    // layer 2
    k_gemm_bn<<<GEMM_GRID, 256>>>(convW + 1 * Hh * Hh, gamma + 1 * Hh, beta + 1 * Hh, 1);
    k_aggstats<<<AGG_GRID, 256>>>(2);

    // pooling (applies layer-2 BN) + MLP
    k_pool<<<Gg, 128>>>(batch, gamma + 2 * Hh, beta + 2 * Hh);
    k_mlp<<<Gg / GPG, 256>>>(mW1, mb1, mW2, mb2, mW3, mb3, out);
}

// round 15
// speedup vs baseline: 1.0322x; 1.0100x over previous
#include <cuda_runtime.h>
#include <cuda_fp16.h>

#define Nn 50000
#define Ee 800000
#define Hh 128
#define Gg 1024
#define EPSb 1e-5f

// ---------------- static device scratch (device-code use only) -------------
__device__ int    d_cnt[Nn];
__device__ int    d_cur[Nn];
__device__ int    d_rowptr[Nn + 1];
__device__ float  d_dinv[Nn];
__device__ int    d_colidx[Ee];
__device__ uint4  d_hbufh[(size_t)Nn * 16];    // N x 128, fp16: h' = dinv[n]*h[n]
__device__ float4 d_aggbuf4[(size_t)Nn * 32];  // N x 128 features, fp32
__device__ float  d_colsum[3 * Hh];            // per-layer BN sums
__device__ float  d_colsq[3 * Hh];
__device__ float  d_pooled[Gg * 256];

// ---------------- init: zero counters + all stat buffers -------------------
__global__ void k_zero_all() {
    int i = blockIdx.x * blockDim.x + threadIdx.x;
    if (i < Nn) { d_cnt[i] = 0; d_cur[i] = 0; }
    if (i < 3 * Hh) { d_colsum[i] = 0.f; d_colsq[i] = 0.f; }
}

// ---------------- CSR construction (edge_index is int32) -------------------
__device__ __forceinline__ int clampN(int v) {
    return v < 0 ? 0 : (v >= Nn ? Nn - 1 : v);
}

__global__ void k_count(const int* __restrict__ ei) {
    int e = blockIdx.x * blockDim.x + threadIdx.x;
    if (e < Ee) atomicAdd(&d_cnt[clampN(ei[Ee + e])], 1);
}

__global__ void k_scan() {   // 1 block, 1024 threads
    __shared__ int ssum[1024];
    int t = threadIdx.x;
    const int CH = (Nn + 1023) / 1024;   // 49
    int b = t * CH;
    int e = min(b + CH, Nn);
    int s = 0;
    for (int i = b; i < e; i++) s += d_cnt[i];
    ssum[t] = s;
    __syncthreads();
    for (int off = 1; off < 1024; off <<= 1) {
        int v = (t >= off) ? ssum[t - off] : 0;
        __syncthreads();
        ssum[t] += v;
        __syncthreads();
    }
    int run = (t > 0) ? ssum[t - 1] : 0;
    for (int i = b; i < e; i++) {
        int c = d_cnt[i];
        d_rowptr[i] = run;
        run += c;
        d_dinv[i] = rsqrtf((float)(c + 1));
    }
    if (t == 0) d_rowptr[Nn] = Ee;
}

__global__ void k_fill(const int* __restrict__ ei) {
    int e = blockIdx.x * blockDim.x + threadIdx.x;
    if (e < Ee) {
        int src = clampN(ei[e]);
        int dst = clampN(ei[Ee + e]);
        int pos = d_rowptr[dst] + atomicAdd(&d_cur[dst], 1);
        d_colidx[pos] = src;
    }
}

// ---------------- GEMM core: outputs h' = dinv[row] * (X@W) in fp16 --------
// block: 256 threads, 64 rows x 128 cols. thread micro-tile: 4 rows x 8 cols.
__device__ __forceinline__ void gemm_core(float (&Xs)[64][129],
                                          float (&Ws)[16][128],
                                          const float* __restrict__ W,
                                          int row0, int tid) {
    int rc = tid & 15, cc = tid >> 4;
    int r0 = rc * 4, c0 = cc * 8;
    float acc[4][8];
#pragma unroll
    for (int i = 0; i < 4; i++)
#pragma unroll
        for (int j = 0; j < 8; j++) acc[i][j] = 0.f;

    for (int kc = 0; kc < 8; kc++) {
        __syncthreads();
        for (int i = tid; i < 16 * 32; i += 256) {
            int kk = i >> 5, c4 = i & 31;
            float4 w = ((const float4*)W)[(size_t)(kc * 16 + kk) * 32 + c4];
            Ws[kk][c4 * 4 + 0] = w.x; Ws[kk][c4 * 4 + 1] = w.y;
            Ws[kk][c4 * 4 + 2] = w.z; Ws[kk][c4 * 4 + 3] = w.w;
        }
        __syncthreads();
#pragma unroll
        for (int kk = 0; kk < 16; kk++) {
            int k = kc * 16 + kk;
            float x0 = Xs[r0 + 0][k];
            float x1 = Xs[r0 + 1][k];
            float x2 = Xs[r0 + 2][k];
            float x3 = Xs[r0 + 3][k];
#pragma unroll
            for (int j = 0; j < 8; j++) {
                float w = Ws[kk][c0 + j];
                acc[0][j] = fmaf(x0, w, acc[0][j]);
                acc[1][j] = fmaf(x1, w, acc[1][j]);
                acc[2][j] = fmaf(x2, w, acc[2][j]);
                acc[3][j] = fmaf(x3, w, acc[3][j]);
            }
        }
    }

#pragma unroll
    for (int i = 0; i < 4; i++) {
        int gr = row0 + r0 + i;
        if (gr < Nn) {
            float di = d_dinv[gr];
            __half2 p0 = __float22half2_rn(make_float2(acc[i][0] * di, acc[i][1] * di));
            __half2 p1 = __float22half2_rn(make_float2(acc[i][2] * di, acc[i][3] * di));
            __half2 p2 = __float22half2_rn(make_float2(acc[i][4] * di, acc[i][5] * di));
            __half2 p3 = __float22half2_rn(make_float2(acc[i][6] * di, acc[i][7] * di));
            uint4 pk;
            pk.x = *(unsigned int*)&p0;
            pk.y = *(unsigned int*)&p1;
            pk.z = *(unsigned int*)&p2;
            pk.w = *(unsigned int*)&p3;
            d_hbufh[(size_t)gr * 16 + cc] = pk;   // 8 fp16 cols at c0
        }
    }
}

// layer 0: X = external input
__global__ __launch_bounds__(256) void k_gemm0(const float* __restrict__ Xin,
                                               const float* __restrict__ W) {
    __shared__ float Xs[64][129];
    __shared__ float Ws[16][128];
    int tid = threadIdx.x;
    int row0 = blockIdx.x * 64;

    for (int i = tid; i < 64 * 32; i += 256) {
        int r = i >> 5, c4 = i & 31;
        int gr = row0 + r;
        float4 v = make_float4(0.f, 0.f, 0.f, 0.f);
        if (gr < Nn) v = ((const float4*)Xin)[(size_t)gr * 32 + c4];
        int c = c4 * 4;
        Xs[r][c + 0] = v.x; Xs[r][c + 1] = v.y;
        Xs[r][c + 2] = v.z; Xs[r][c + 3] = v.w;
    }
    gemm_core(Xs, Ws, W, row0, tid);
}

// layers 1,2: X = d_aggbuf4 (fp32) with fused BN(from stats slot sl)+ReLU
__global__ __launch_bounds__(256) void k_gemm_bn(const float* __restrict__ W,
                                                 const float* __restrict__ gamma,
                                                 const float* __restrict__ beta,
                                                 int sl) {
    __shared__ float Xs[64][129];
    __shared__ float Ws[16][128];
    __shared__ float ssc[128], ssh[128];
    int tid = threadIdx.x;
    int row0 = blockIdx.x * 64;

    if (tid < 128) {   // compute BN scale/shift from layer-sl statistics
        float mean = d_colsum[sl * Hh + tid] * (1.f / (float)Nn);
        float var = d_colsq[sl * Hh + tid] * (1.f / (float)Nn) - mean * mean;
        var = fmaxf(var, 0.f);
        float sc = gamma[tid] * rsqrtf(var + EPSb);
        ssc[tid] = sc;
        ssh[tid] = beta[tid] - mean * sc;
    }
    __syncthreads();

    for (int i = tid; i < 64 * 32; i += 256) {
        int r = i >> 5, c4 = i & 31;
        int gr = row0 + r;
        float4 v = make_float4(0.f, 0.f, 0.f, 0.f);
        if (gr < Nn) v = d_aggbuf4[(size_t)gr * 32 + c4];
        int c = c4 * 4;
        Xs[r][c + 0] = fmaxf(fmaf(v.x, ssc[c + 0], ssh[c + 0]), 0.f);
        Xs[r][c + 1] = fmaxf(fmaf(v.y, ssc[c + 1], ssh[c + 1]), 0.f);
        Xs[r][c + 2] = fmaxf(fmaf(v.z, ssc[c + 2], ssh[c + 2]), 0.f);
        Xs[r][c + 3] = fmaxf(fmaf(v.w, ssc[c + 3], ssh[c + 3]), 0.f);
    }
    gemm_core(Xs, Ws, W, row0, tid);
}

// --------- gather aggregation (unweighted fp16 h' reads) + BN statistics ---
// agg_n = dinv[n] * (h'[n] + sum_j h'[src_j]); no weights in the inner loop.
__global__ __launch_bounds__(256) void k_aggstats(int layer) {
    __shared__ float4 psum[8][32];
    __shared__ float4 psq[8][32];
    int tid = threadIdx.x;
    int warp = tid >> 5, lane = tid & 31;
    int n = blockIdx.x * 8 + warp;
    const uint2* hb2 = (const uint2*)d_hbufh;

    float4 acc = make_float4(0.f, 0.f, 0.f, 0.f);
    if (n < Nn) {
        {   // self term: h'[n]
            uint2 hu = hb2[(size_t)n * 32 + lane];
            float2 f0 = __half22float2(*reinterpret_cast<__half2*>(&hu.x));
            float2 f1 = __half22float2(*reinterpret_cast<__half2*>(&hu.y));
            acc.x = f0.x; acc.y = f0.y; acc.z = f1.x; acc.w = f1.y;
        }
        float4 acc2 = make_float4(0.f, 0.f, 0.f, 0.f);

        int beg = d_rowptr[n], end = d_rowptr[n + 1];
        for (int base = beg; base < end; base += 32) {
            int m = min(32, end - base);
            int s = 0;
            if (lane < m) s = d_colidx[base + lane];
            int j = 0;
            for (; j + 1 < m; j += 2) {
                int sA = __shfl_sync(0xffffffffu, s, j);
                int sB = __shfl_sync(0xffffffffu, s, j + 1);
                uint2 huA = hb2[(size_t)sA * 32 + lane];
                uint2 huB = hb2[(size_t)sB * 32 + lane];
                float2 a0 = __half22float2(*reinterpret_cast<__half2*>(&huA.x));
                float2 a1 = __half22float2(*reinterpret_cast<__half2*>(&huA.y));
                float2 b0 = __half22float2(*reinterpret_cast<__half2*>(&huB.x));
                float2 b1 = __half22float2(*reinterpret_cast<__half2*>(&huB.y));
                acc.x += a0.x; acc.y += a0.y; acc.z += a1.x; acc.w += a1.y;
                acc2.x += b0.x; acc2.y += b0.y; acc2.z += b1.x; acc2.w += b1.y;
            }
            if (j < m) {
                int sA = __shfl_sync(0xffffffffu, s, j);
                uint2 huA = hb2[(size_t)sA * 32 + lane];
                float2 a0 = __half22float2(*reinterpret_cast<__half2*>(&huA.x));
                float2 a1 = __half22float2(*reinterpret_cast<__half2*>(&huA.y));
                acc.x += a0.x; acc.y += a0.y; acc.z += a1.x; acc.w += a1.y;
            }
        }
        // merge + final scale by dinv[n]
        float di = d_dinv[n];
        acc.x = (acc.x + acc2.x) * di;
        acc.y = (acc.y + acc2.y) * di;
        acc.z = (acc.z + acc2.z) * di;
        acc.w = (acc.w + acc2.w) * di;
        d_aggbuf4[(size_t)n * 32 + lane] = acc;
    }

    psum[warp][lane] = acc;
    psq[warp][lane] = make_float4(acc.x * acc.x, acc.y * acc.y,
                                  acc.z * acc.z, acc.w * acc.w);
    __syncthreads();

    if (tid < 128) {
        int c4 = tid >> 2, comp = tid & 3;
        float s = 0.f, q = 0.f;
#pragma unroll
        for (int w = 0; w < 8; w++) {
            const float* a = (const float*)&psum[w][c4];
            const float* b = (const float*)&psq[w][c4];
            s += a[comp];
            q += b[comp];
        }
        atomicAdd(&d_colsum[layer * Hh + tid], s);
        atomicAdd(&d_colsq[layer * Hh + tid], q);
    }
}

// ---------------- pooling: one block per graph, binary search --------------
// applies layer-2 BN+ReLU inline; batch is int32, sorted.
__global__ __launch_bounds__(128) void k_pool(const int* __restrict__ batch,
                                              const float* __restrict__ gamma,
                                              const float* __restrict__ beta) {
    __shared__ int sbound[2];
    int g = blockIdx.x;
    int t = threadIdx.x;   // t = feature col
    if (t < 2) {
        int target = g + t;  // lower_bound(target)
        int lo = 0, hi = Nn;
        while (lo < hi) {
            int mid = (lo + hi) >> 1;
            if (batch[mid] < target) lo = mid + 1;
            else hi = mid;
        }
        sbound[t] = lo;
    }
    float mean = d_colsum[2 * Hh + t] * (1.f / (float)Nn);
    float var = d_colsq[2 * Hh + t] * (1.f / (float)Nn) - mean * mean;
    var = fmaxf(var, 0.f);
    float sc = gamma[t] * rsqrtf(var + EPSb);
    float sh = beta[t] - mean * sc;
    __syncthreads();

    int lo = sbound[0], hi = sbound[1];
    const float* agg = (const float*)d_aggbuf4;
    float rsum = 0.f, rmax = 0.f;
    for (int n = lo; n < hi; n++) {
        float v = fmaxf(fmaf(agg[(size_t)n * 128 + t], sc, sh), 0.f);
        rsum += v;
        rmax = fmaxf(rmax, v);
    }
    int cnt = hi - lo;
    d_pooled[g * 256 + t] = (cnt > 0) ? rsum / (float)cnt : 0.f;
    d_pooled[g * 256 + 128 + t] = (cnt > 0) ? rmax : 0.f;
}

// ---------------- MLP head: 8 graphs per block -----------------------------
#define GPG 8
__global__ __launch_bounds__(256) void k_mlp(const float* __restrict__ mW1,
                                             const float* __restrict__ mb1,
                                             const float* __restrict__ mW2,
                                             const float* __restrict__ mb2,
                                             const float* __restrict__ mW3,
                                             const float* __restrict__ mb3,
                                             float* __restrict__ out) {
    __shared__ float sg[GPG][256];
    __shared__ float h1[GPG][256];
    __shared__ float h2[GPG][128];
    int t = threadIdx.x;
    int g0 = blockIdx.x * GPG;

#pragma unroll
    for (int g = 0; g < GPG; g++)
        sg[g][t] = d_pooled[(g0 + g) * 256 + t];
    __syncthreads();

    {
        float acc[GPG];
        float b = mb1[t];
#pragma unroll
        for (int g = 0; g < GPG; g++) acc[g] = b;
        for (int k = 0; k < 256; k++) {
            float wv = mW1[k * 256 + t];
#pragma unroll
            for (int g = 0; g < GPG; g++) acc[g] = fmaf(sg[g][k], wv, acc[g]);
        }
#pragma unroll
        for (int g = 0; g < GPG; g++) h1[g][t] = fmaxf(acc[g], 0.f);
    }
    __syncthreads();

    if (t < 128) {
        float acc[GPG];
        float b = mb2[t];
#pragma unroll
        for (int g = 0; g < GPG; g++) acc[g] = b;
        for (int k = 0; k < 256; k++) {
            float wv = mW2[k * 128 + t];
#pragma unroll
            for (int g = 0; g < GPG; g++) acc[g] = fmaf(h1[g][k], wv, acc[g]);
        }
#pragma unroll
        for (int g = 0; g < GPG; g++) h2[g][t] = fmaxf(acc[g], 0.f);
    }
    __syncthreads();

    if (t < GPG) {
        float a = mb3[0];
        for (int i = 0; i < 128; i++) a = fmaf(h2[t][i], mW3[i], a);
        out[g0 + t] = a;
    }
}

// ---------------- launcher ----------------
extern "C" void kernel_launch(void* const* d_in, const int* in_sizes, int n_in,
                              void* d_out, int out_size) {
    const float* x      = (const float*)d_in[0];
    const int* ei       = (const int*)d_in[1];     // int32
    const int* batch    = (const int*)d_in[2];     // int32, sorted
    const float* convW0 = (const float*)d_in[3];
    const float* convW  = (const float*)d_in[4];
    // d_in[5] = convb : cancels inside batchnorm, unused
    const float* gamma  = (const float*)d_in[6];
    const float* beta   = (const float*)d_in[7];
    const float* mW1    = (const float*)d_in[8];
    const float* mb1    = (const float*)d_in[9];
    const float* mW2    = (const float*)d_in[10];
    const float* mb2    = (const float*)d_in[11];
    const float* mW3    = (const float*)d_in[12];
    const float* mb3    = (const float*)d_in[13];
    float* out = (float*)d_out;

    // CSR construction (scan computes dinv, needed by GEMM epilogues)
    k_zero_all<<<(Nn + 255) / 256, 256>>>();
    k_count<<<(Ee + 255) / 256, 256>>>(ei);
    k_scan<<<1, 1024>>>();
    k_fill<<<(Ee + 255) / 256, 256>>>(ei);

    const int GEMM_GRID = (Nn + 63) / 64;   // 782
    const int AGG_GRID = (Nn + 7) / 8;      // 6250

    // layer 0
    k_gemm0<<<GEMM_GRID, 256>>>(x, convW0);
    k_aggstats<<<AGG_GRID, 256>>>(0);
    // layer 1
    k_gemm_bn<<<GEMM_GRID, 256>>>(convW + 0 * Hh * Hh, gamma + 0 * Hh, beta + 0 * Hh, 0);
    k_aggstats<<<AGG_GRID, 256>>>(1);
    // layer 2
    k_gemm_bn<<<GEMM_GRID, 256>>>(convW + 1 * Hh * Hh, gamma + 1 * Hh, beta + 1 * Hh, 1);
    k_aggstats<<<AGG_GRID, 256>>>(2);

    // pooling (applies layer-2 BN) + MLP
    k_pool<<<Gg, 128>>>(batch, gamma + 2 * Hh, beta + 2 * Hh);
    k_mlp<<<Gg / GPG, 256>>>(mW1, mb1, mW2, mb2, mW3, mb3, out);
}